// round 6
// baseline (speedup 1.0000x reference)
#include <cuda_runtime.h>
#include <cuda_fp16.h>
#include <cstdint>

#define Ndim 1024
#define Mdim 1024
#define Tdim 64
#define Ddim 128

#define BN 64
#define BM 64
#define BT 8
#define KC 16             // halves per K chunk
#define NKC (Ddim / KC)   // 8
#define NSTAGE 3
#define PADK 24           // smem row stride in halves (48B; 12-word stride = conflict-free)
#define THREADS 1024

#define A_STAGE (BT * BN * PADK * 2)          // 24576 B
#define STAGE_BYTES (2 * A_STAGE)             // 49152 B (A then B)
#define SMEM_TOTAL (NSTAGE * STAGE_BYTES)     // 147456 B
#define STAGE_T_STRIDE (BN * 66)              // floats per t-plane in epilogue overlay

__device__ float  g_s1[Ndim * Tdim];
__device__ float  g_s2[Mdim * Tdim];
__device__ __half g_h1[(size_t)Ndim * Tdim * Ddim];
__device__ __half g_h2[(size_t)Mdim * Tdim * Ddim];

// ---------------- helpers ----------------
__device__ __forceinline__ uint32_t smem_u32(const void* p) {
    uint32_t a;
    asm("{ .reg .u64 t; cvta.to.shared.u64 t, %1; cvt.u32.u64 %0, t; }" : "=r"(a) : "l"(p));
    return a;
}
__device__ __forceinline__ void cp_async16(uint32_t dst, const void* src) {
    asm volatile("cp.async.cg.shared.global [%0], [%1], 16;" :: "r"(dst), "l"(src));
}
__device__ __forceinline__ void cp_commit() {
    asm volatile("cp.async.commit_group;" ::: "memory");
}
template <int N>
__device__ __forceinline__ void cp_wait() {
    asm volatile("cp.async.wait_group %0;" :: "n"(N) : "memory");
}

__device__ __forceinline__ void mma16816(float* c, uint32_t a0, uint32_t a1,
                                         uint32_t a2, uint32_t a3,
                                         uint32_t b0, uint32_t b1) {
    asm volatile(
        "mma.sync.aligned.m16n8k16.row.col.f32.f16.f16.f32 "
        "{%0,%1,%2,%3}, {%4,%5,%6,%7}, {%8,%9}, {%0,%1,%2,%3};\n"
        : "+f"(c[0]), "+f"(c[1]), "+f"(c[2]), "+f"(c[3])
        : "r"(a0), "r"(a1), "r"(a2), "r"(a3), "r"(b0), "r"(b1));
}

// ---------------------------------------------------------------------------
// Kernel 1: fused fp16 convert + squared row norms. One warp per (row, t).
// ---------------------------------------------------------------------------
__global__ void prep_kernel(const float* __restrict__ X1,
                            const float* __restrict__ X2) {
    int gwarp = (blockIdx.x * blockDim.x + threadIdx.x) >> 5;
    int lane  = threadIdx.x & 31;
    const float* src;
    float* ndst;
    __half* hdst;
    int row;
    if (gwarp < Ndim * Tdim) { src = X1; ndst = g_s1; hdst = g_h1; row = gwarp; }
    else                     { src = X2; ndst = g_s2; hdst = g_h2; row = gwarp - Ndim * Tdim; }
    const float4 v = *((const float4*)(src + (size_t)row * Ddim) + lane);
    __half2 h01 = __floats2half2_rn(v.x, v.y);
    __half2 h23 = __floats2half2_rn(v.z, v.w);
    uint2 packed;
    packed.x = *(uint32_t*)&h01;
    packed.y = *(uint32_t*)&h23;
    *(uint2*)(hdst + (size_t)row * Ddim + lane * 4) = packed;
    float s = v.x * v.x + v.y * v.y + v.z * v.z + v.w * v.w;
    #pragma unroll
    for (int o = 16; o > 0; o >>= 1) s += __shfl_down_sync(0xffffffffu, s, o);
    if (lane == 0) ndst[row] = s;
}

// ---------------------------------------------------------------------------
// Kernel 2: batched cross-GEMM via mma.sync, 3-stage cp.async pipeline.
// CTA: 1024 threads = 32 warps = 8 t-planes x 2 n-halves x 2 m-halves.
// CTA tile: 64n x 64m x 8t. Warp tile: 32n x 32m (one t). 32 accums/thread.
// ---------------------------------------------------------------------------
__global__ __launch_bounds__(THREADS, 1)
void cross_mma_kernel(float* __restrict__ Y) {
    extern __shared__ char smem[];
    const uint32_t sbase = smem_u32(smem);

    const int tid  = threadIdx.x;
    const int lane = tid & 31;
    const int wid  = tid >> 5;
    const int tp   = wid >> 2;          // t-plane 0..7
    const int nq   = (wid >> 1) & 1;    // n-half
    const int mq   = wid & 1;           // m-half

    const int m0 = blockIdx.x * BM;
    const int n0 = blockIdx.y * BN;
    const int t0 = blockIdx.z * BT;

    const int lr = lane >> 2;           // 0..7
    const int lc = (lane & 3) * 2;      // 0,2,4,6

    float acc[2][4][4];
    #pragma unroll
    for (int i = 0; i < 2; ++i)
        #pragma unroll
        for (int j = 0; j < 4; ++j)
            #pragma unroll
            for (int q = 0; q < 4; ++q) acc[i][j][q] = 0.0f;

    // loader precomputed indices: each thread moves 1 A float4 + 1 B float4
    const int lk4 = tid & 1;            // which 8-half segment of the 16-chunk
    const int lrow = (tid >> 1) & 63;
    const int lt = tid >> 7;
    const size_t ga_base = ((size_t)(n0 + lrow) * Tdim + (t0 + lt)) * Ddim + lk4 * 8;
    const size_t gb_base = ((size_t)(m0 + lrow) * Tdim + (t0 + lt)) * Ddim + lk4 * 8;
    const uint32_t sa_off = (uint32_t)((lt * BN + lrow) * (PADK * 2) + lk4 * 16);

    auto load_stage = [&](int cc, int buf) {
        const uint32_t ab = sbase + buf * STAGE_BYTES;
        cp_async16(ab + sa_off, g_h1 + ga_base + cc * KC);
        cp_async16(ab + A_STAGE + sa_off, g_h2 + gb_base + cc * KC);
        cp_commit();
    };

    load_stage(0, 0);
    load_stage(1, 1);

    int buf = 0;
    for (int cc = 0; cc < NKC; ++cc) {
        if (cc < NKC - 1) cp_wait<1>();   // stage cc landed
        else              cp_wait<0>();
        __syncthreads();                  // all warps done with stage cc-1's buffer
        if (cc + 2 < NKC) load_stage(cc + 2, (cc + 2) % NSTAGE);

        const __half* As = (const __half*)(smem + buf * STAGE_BYTES) + tp * (BN * PADK);
        const __half* Bs = (const __half*)(smem + buf * STAGE_BYTES + A_STAGE) + tp * (BM * PADK);

        uint32_t b0[4], b1[4];
        #pragma unroll
        for (int mi = 0; mi < 4; ++mi) {
            const __half* bp = Bs + (mq * 32 + mi * 8 + lr) * PADK + lc;
            b0[mi] = *(const uint32_t*)(bp);
            b1[mi] = *(const uint32_t*)(bp + 8);
        }
        #pragma unroll
        for (int ni = 0; ni < 2; ++ni) {
            const __half* ap = As + (nq * 32 + ni * 16 + lr) * PADK + lc;
            uint32_t a0 = *(const uint32_t*)(ap);
            uint32_t a1 = *(const uint32_t*)(ap + 8 * PADK);
            uint32_t a2 = *(const uint32_t*)(ap + 8);
            uint32_t a3 = *(const uint32_t*)(ap + 8 * PADK + 8);
            #pragma unroll
            for (int mi = 0; mi < 4; ++mi)
                mma16816(acc[ni][mi], a0, a1, a2, a3, b0[mi], b1[mi]);
        }
        buf = (buf + 1 == NSTAGE) ? 0 : buf + 1;
    }
    __syncthreads();   // compute fully done; smem reusable as epilogue stage

    // ---- epilogue: combine with norms, stage [t][n][66] in smem ----
    const float invD = 1.0f / (float)Ddim;
    const int tt = t0 + tp;
    float s1a[2], s1b[2], s2a[4], s2b[4];
    #pragma unroll
    for (int ni = 0; ni < 2; ++ni) {
        int ng = n0 + nq * 32 + ni * 16 + lr;
        s1a[ni] = __ldg(&g_s1[ng * Tdim + tt]);
        s1b[ni] = __ldg(&g_s1[(ng + 8) * Tdim + tt]);
    }
    #pragma unroll
    for (int mi = 0; mi < 4; ++mi) {
        int mg = m0 + mq * 32 + mi * 8 + lc;
        s2a[mi] = __ldg(&g_s2[mg * Tdim + tt]);
        s2b[mi] = __ldg(&g_s2[(mg + 1) * Tdim + tt]);
    }

    float* stage = (float*)smem;
    float* plane = stage + tp * STAGE_T_STRIDE;
    #pragma unroll
    for (int ni = 0; ni < 2; ++ni) {
        #pragma unroll
        for (int mi = 0; mi < 4; ++mi) {
            int r  = nq * 32 + ni * 16 + lr;
            int m2 = mq * 32 + mi * 8 + lc;
            float2 v0, v1;
            v0.x = (s1a[ni] + s2a[mi] - 2.0f * acc[ni][mi][0]) * invD;
            v0.y = (s1a[ni] + s2b[mi] - 2.0f * acc[ni][mi][1]) * invD;
            v1.x = (s1b[ni] + s2a[mi] - 2.0f * acc[ni][mi][2]) * invD;
            v1.y = (s1b[ni] + s2b[mi] - 2.0f * acc[ni][mi][3]) * invD;
            *(float2*)(plane + r * 66 + m2)       = v0;
            *(float2*)(plane + (r + 8) * 66 + m2) = v1;
        }
    }
    __syncthreads();

    // ---- writeback: full 32B sector (8 t's) per (n,m) ----
    #pragma unroll
    for (int it = 0; it < 4; ++it) {
        int p = tid + it * THREADS;    // 0..4095
        int n = p >> 6;
        int m = p & 63;
        float v[8];
        #pragma unroll
        for (int t = 0; t < 8; ++t) v[t] = stage[t * STAGE_T_STRIDE + n * 66 + m];
        float4 w0, w1;
        w0.x = v[0]; w0.y = v[1]; w0.z = v[2]; w0.w = v[3];
        w1.x = v[4]; w1.y = v[5]; w1.z = v[6]; w1.w = v[7];
        size_t off = ((size_t)(n0 + n) * Mdim + (m0 + m)) * Tdim + t0;
        *(float4*)(Y + off)     = w0;
        *(float4*)(Y + off + 4) = w1;
    }
}

// ---------------------------------------------------------------------------
extern "C" void kernel_launch(void* const* d_in, const int* in_sizes, int n_in,
                              void* d_out, int out_size) {
    const float* X1 = (const float*)d_in[0];
    const float* X2 = (const float*)d_in[1];
    float* Y = (float*)d_out;

    int total_warps = 2 * Ndim * Tdim;
    int blocks = (total_warps * 32) / 256;
    prep_kernel<<<blocks, 256>>>(X1, X2);

    cudaFuncSetAttribute(cross_mma_kernel,
                         cudaFuncAttributeMaxDynamicSharedMemorySize, SMEM_TOTAL);
    dim3 grid(Mdim / BM, Ndim / BN, Tdim / BT);   // 16 x 16 x 8 = 2048 CTAs
    cross_mma_kernel<<<grid, THREADS, SMEM_TOTAL>>>(Y);
}

// round 7
// speedup vs baseline: 1.4634x; 1.4634x over previous
#include <cuda_runtime.h>
#include <cuda_fp16.h>
#include <cstdint>

#define Ndim 1024
#define Mdim 1024
#define Tdim 64
#define Ddim 128

#define BN 64
#define BM 64
#define BT 4
#define KC 32            // halves per K chunk
#define NKC (Ddim / KC)  // 4
#define PADK 40          // padded smem row stride in halves (80B: conflict-free frags)
#define THREADS 256

#define A_BYTES (BT * BN * PADK * 2)      // 20480
#define B_BYTES (BT * BM * PADK * 2)      // 20480
#define BUF_BYTES (A_BYTES + B_BYTES)     // 40960
#define SMEM_TOTAL (2 * BUF_BYTES)        // 81920 (epilogue stage overlays this)
#define STAGE_T_STRIDE (BN * 66)          // floats per t-plane (padded 66)

__device__ float  g_s1[Ndim * Tdim];
__device__ float  g_s2[Mdim * Tdim];
__device__ __half g_h1[(size_t)Ndim * Tdim * Ddim];
__device__ __half g_h2[(size_t)Mdim * Tdim * Ddim];

// ---------------- helpers ----------------
__device__ __forceinline__ uint32_t smem_u32(const void* p) {
    uint32_t a;
    asm("{ .reg .u64 t; cvta.to.shared.u64 t, %1; cvt.u32.u64 %0, t; }" : "=r"(a) : "l"(p));
    return a;
}
__device__ __forceinline__ void cp_async16(uint32_t dst, const void* src) {
    asm volatile("cp.async.cg.shared.global [%0], [%1], 16;" :: "r"(dst), "l"(src));
}
__device__ __forceinline__ void cp_commit() {
    asm volatile("cp.async.commit_group;" ::: "memory");
}
template <int N>
__device__ __forceinline__ void cp_wait() {
    asm volatile("cp.async.wait_group %0;" :: "n"(N) : "memory");
}

__device__ __forceinline__ void mma16816(float* c, uint32_t a0, uint32_t a1,
                                         uint32_t a2, uint32_t a3,
                                         uint32_t b0, uint32_t b1) {
    asm volatile(
        "mma.sync.aligned.m16n8k16.row.col.f32.f16.f16.f32 "
        "{%0,%1,%2,%3}, {%4,%5,%6,%7}, {%8,%9}, {%0,%1,%2,%3};\n"
        : "+f"(c[0]), "+f"(c[1]), "+f"(c[2]), "+f"(c[3])
        : "r"(a0), "r"(a1), "r"(a2), "r"(a3), "r"(b0), "r"(b1));
}

// ---------------------------------------------------------------------------
// Kernel 1: fused fp16 convert + squared row norms. One warp per (row, t).
// ---------------------------------------------------------------------------
__global__ void prep_kernel(const float* __restrict__ X1,
                            const float* __restrict__ X2) {
    int gwarp = (blockIdx.x * blockDim.x + threadIdx.x) >> 5;
    int lane  = threadIdx.x & 31;
    const float* src;
    float* ndst;
    __half* hdst;
    int row;
    if (gwarp < Ndim * Tdim) { src = X1; ndst = g_s1; hdst = g_h1; row = gwarp; }
    else                     { src = X2; ndst = g_s2; hdst = g_h2; row = gwarp - Ndim * Tdim; }
    const float4 v = *((const float4*)(src + (size_t)row * Ddim) + lane);
    __half2 h01 = __floats2half2_rn(v.x, v.y);
    __half2 h23 = __floats2half2_rn(v.z, v.w);
    uint2 packed;
    packed.x = *(uint32_t*)&h01;
    packed.y = *(uint32_t*)&h23;
    *(uint2*)(hdst + (size_t)row * Ddim + lane * 4) = packed;
    float s = v.x * v.x + v.y * v.y + v.z * v.z + v.w * v.w;
    #pragma unroll
    for (int o = 16; o > 0; o >>= 1) s += __shfl_down_sync(0xffffffffu, s, o);
    if (lane == 0) ndst[row] = s;
}

// ---------------------------------------------------------------------------
// Kernel 2: batched cross-GEMM via mma.sync. 2 CTAs/SM for barrier overlap.
// CTA: 256 threads = 8 warps = 4 t-planes x 2 m-halves.
// CTA tile: 64n x 64m x 4t. Warp tile: 64n x 32m (one t).
// Grid: t fastest so half-sector writes of adjacent t-chunks merge in L2.
// ---------------------------------------------------------------------------
__global__ __launch_bounds__(THREADS, 2)
void cross_mma_kernel(float* __restrict__ Y) {
    extern __shared__ char smem[];
    const uint32_t sbase = smem_u32(smem);

    const int tid  = threadIdx.x;
    const int lane = tid & 31;
    const int wid  = tid >> 5;
    const int tp   = wid >> 1;   // t-plane 0..3
    const int mh   = wid & 1;    // m-half 0..1

    const int t0 = blockIdx.x * BT;
    const int m0 = blockIdx.y * BM;
    const int n0 = blockIdx.z * BN;

    const int lr = lane >> 2;          // 0..7
    const int lc = (lane & 3) * 2;     // 0,2,4,6

    float acc[4][4][4];
    #pragma unroll
    for (int i = 0; i < 4; ++i)
        #pragma unroll
        for (int j = 0; j < 4; ++j)
            #pragma unroll
            for (int q = 0; q < 4; ++q) acc[i][j][q] = 0.0f;

    // ---- cp.async loader: 2048 float4 per stage / 256 thr = 8 each ----
    auto load_stage = [&](int cc, int buf) {
        const uint32_t abase = sbase + buf * BUF_BYTES;
        const uint32_t bbase = abase + A_BYTES;
        #pragma unroll
        for (int it = 0; it < 8; ++it) {
            int i = tid + it * THREADS;          // 0..2047
            if (i < 1024) {
                int k4 = i & 3, n = (i >> 2) & 63, t = i >> 8;
                const __half* g = g_h1 + ((size_t)(n0 + n) * Tdim + (t0 + t)) * Ddim
                                  + cc * KC + k4 * 8;
                cp_async16(abase + t * (BN * PADK * 2) + n * (PADK * 2) + k4 * 16, g);
            } else {
                int j = i - 1024;
                int k4 = j & 3, m = (j >> 2) & 63, t = j >> 8;
                const __half* g = g_h2 + ((size_t)(m0 + m) * Tdim + (t0 + t)) * Ddim
                                  + cc * KC + k4 * 8;
                cp_async16(bbase + t * (BM * PADK * 2) + m * (PADK * 2) + k4 * 16, g);
            }
        }
        cp_commit();
    };

    load_stage(0, 0);

    for (int cc = 0; cc < NKC; ++cc) {
        // prefetch next chunk into the other buffer (freed by trailing sync of
        // the previous iteration), then wait for the oldest group (= chunk cc)
        if (cc + 1 < NKC) {
            load_stage(cc + 1, (cc + 1) & 1);
            cp_wait<1>();
        } else {
            cp_wait<0>();
        }
        __syncthreads();      // chunk cc visible to all warps

        const int buf = cc & 1;
        const __half* Ah = (const __half*)(smem + buf * BUF_BYTES) + tp * (BN * PADK);
        const __half* Bh = (const __half*)(smem + buf * BUF_BYTES + A_BYTES) + tp * (BM * PADK);

        #pragma unroll
        for (int s = 0; s < 2; ++s) {     // two k16 steps per 32-chunk
            const int kb = s * 16;
            uint32_t b0[4], b1[4];
            #pragma unroll
            for (int mi = 0; mi < 4; ++mi) {
                const __half* bp = Bh + (mh * 32 + mi * 8 + lr) * PADK + kb + lc;
                b0[mi] = *(const uint32_t*)(bp);
                b1[mi] = *(const uint32_t*)(bp + 8);
            }
            #pragma unroll
            for (int ni = 0; ni < 4; ++ni) {
                const __half* ap = Ah + (ni * 16 + lr) * PADK + kb + lc;
                uint32_t a0 = *(const uint32_t*)(ap);
                uint32_t a1 = *(const uint32_t*)(ap + 8 * PADK);
                uint32_t a2 = *(const uint32_t*)(ap + 8);
                uint32_t a3 = *(const uint32_t*)(ap + 8 * PADK + 8);
                #pragma unroll
                for (int mi = 0; mi < 4; ++mi)
                    mma16816(acc[ni][mi], a0, a1, a2, a3, b0[mi], b1[mi]);
            }
        }
        __syncthreads();      // all warps done with buf before it is overwritten
    }

    // ---- epilogue: combine with norms, stage [t][n][66] in smem ----
    const float invD = 1.0f / (float)Ddim;
    const int tt = t0 + tp;
    float s1a[4], s1b[4], s2a[4], s2b[4];
    #pragma unroll
    for (int ni = 0; ni < 4; ++ni) {
        s1a[ni] = __ldg(&g_s1[(n0 + ni * 16 + lr) * Tdim + tt]);
        s1b[ni] = __ldg(&g_s1[(n0 + ni * 16 + lr + 8) * Tdim + tt]);
    }
    #pragma unroll
    for (int mi = 0; mi < 4; ++mi) {
        int mg = m0 + mh * 32 + mi * 8 + lc;
        s2a[mi] = __ldg(&g_s2[mg * Tdim + tt]);
        s2b[mi] = __ldg(&g_s2[(mg + 1) * Tdim + tt]);
    }

    float* stage = (float*)smem;
    float* plane = stage + tp * STAGE_T_STRIDE;
    #pragma unroll
    for (int ni = 0; ni < 4; ++ni) {
        #pragma unroll
        for (int mi = 0; mi < 4; ++mi) {
            int r  = ni * 16 + lr;
            int m2 = mh * 32 + mi * 8 + lc;
            float2 v0, v1;
            v0.x = (s1a[ni] + s2a[mi] - 2.0f * acc[ni][mi][0]) * invD;
            v0.y = (s1a[ni] + s2b[mi] - 2.0f * acc[ni][mi][1]) * invD;
            v1.x = (s1b[ni] + s2a[mi] - 2.0f * acc[ni][mi][2]) * invD;
            v1.y = (s1b[ni] + s2b[mi] - 2.0f * acc[ni][mi][3]) * invD;
            *(float2*)(plane + r * 66 + m2)       = v0;
            *(float2*)(plane + (r + 8) * 66 + m2) = v1;
        }
    }
    __syncthreads();

    // ---- writeback: 16B (4 t's) per (n,m); adjacent-t CTA supplies the
    //      other half of the 32B sector (t is the fastest grid dim) ----
    #pragma unroll
    for (int it = 0; it < 16; ++it) {
        int p = tid + it * THREADS;    // 0..4095
        int n = p >> 6;
        int m = p & 63;
        float4 w;
        w.x = stage[0 * STAGE_T_STRIDE + n * 66 + m];
        w.y = stage[1 * STAGE_T_STRIDE + n * 66 + m];
        w.z = stage[2 * STAGE_T_STRIDE + n * 66 + m];
        w.w = stage[3 * STAGE_T_STRIDE + n * 66 + m];
        size_t off = ((size_t)(n0 + n) * Mdim + (m0 + m)) * Tdim + t0;
        *(float4*)(Y + off) = w;
    }
}

// ---------------------------------------------------------------------------
extern "C" void kernel_launch(void* const* d_in, const int* in_sizes, int n_in,
                              void* d_out, int out_size) {
    const float* X1 = (const float*)d_in[0];
    const float* X2 = (const float*)d_in[1];
    float* Y = (float*)d_out;

    int total_warps = 2 * Ndim * Tdim;
    int blocks = (total_warps * 32) / 256;
    prep_kernel<<<blocks, 256>>>(X1, X2);

    cudaFuncSetAttribute(cross_mma_kernel,
                         cudaFuncAttributeMaxDynamicSharedMemorySize, SMEM_TOTAL);
    dim3 grid(Tdim / BT, Mdim / BM, Ndim / BN);   // 16 x 16 x 16, t fastest
    cross_mma_kernel<<<grid, THREADS, SMEM_TOTAL>>>(Y);
}